// round 12
// baseline (speedup 1.0000x reference)
#include <cuda_runtime.h>
#include <cuda_fp16.h>
#include <cuda_bf16.h>
#include <cstdint>

#define B_ 4
#define T_ 2048
#define C_ 2048
#define H_ 32
#define M_ (B_*T_)
#define NTOT (M_*C_)
#define WSZ (C_*C_)
#define EPS_ 0.00064f
#define PCH 68   /* floats per row: 272B, 16B-aligned */

// ---------------- scratch (static device globals; allocation-free) ----------------
__device__ __half g_xrh[NTOT], g_xrl[NTOT];
__device__ __half g_xkh[NTOT], g_xkl[NTOT];
__device__ __half g_xvh[NTOT], g_xvl[NTOT];
__device__ __half g_xgh[NTOT];
__device__ __half g_zh[NTOT];
__device__ float g_r[NTOT], g_k[NTOT], g_v[NTOT], g_gt[NTOT];
__device__ float g_S[128 * 32 * 4096];
__device__ float g_po[128 * 32 * 4096];
__device__ __half g_wrh[WSZ], g_wrl[WSZ];
__device__ __half g_wkh[WSZ], g_wkl[WSZ];
__device__ __half g_wvh[WSZ], g_wvl[WSZ];
__device__ __half g_wgh[WSZ], g_wgl[WSZ];
__device__ __half g_woh[WSZ], g_wol[WSZ];

// ---------------- PTX helpers (baseline PTX only) ----------------
__device__ __forceinline__ uint32_t smem_u32(const void* p) {
    uint32_t a;
    asm("{ .reg .u64 t; cvta.to.shared.u64 t, %1; cvt.u32.u64 %0, t; }" : "=r"(a) : "l"(p));
    return a;
}
#define CPASYNC16(dst, src) \
    asm volatile("cp.async.cg.shared.global [%0], [%1], 16;" :: "r"(dst), "l"(src))
#define CPCOMMIT() asm volatile("cp.async.commit_group;" ::: "memory")
#define CPWAIT1()  asm volatile("cp.async.wait_group 1;" ::: "memory")
#define CPWAIT0()  asm volatile("cp.async.wait_group 0;" ::: "memory")

__device__ __forceinline__ void ldsm_x4(uint32_t* r, uint32_t addr) {
    asm volatile("ldmatrix.sync.aligned.m8n8.x4.shared.b16 {%0,%1,%2,%3}, [%4];"
                 : "=r"(r[0]), "=r"(r[1]), "=r"(r[2]), "=r"(r[3]) : "r"(addr));
}
__device__ __forceinline__ void mma_f16(float* c, const uint32_t* a, const uint32_t* b) {
    asm volatile(
        "mma.sync.aligned.m16n8k16.row.col.f32.f16.f16.f32 "
        "{%0,%1,%2,%3}, {%4,%5,%6,%7}, {%8,%9}, {%0,%1,%2,%3};"
        : "+f"(c[0]), "+f"(c[1]), "+f"(c[2]), "+f"(c[3])
        : "r"(a[0]), "r"(a[1]), "r"(a[2]), "r"(a[3]), "r"(b[0]), "r"(b[1]));
}

// smem tile: 128 rows x 64 fp16 = 128B/row; 8 chunks of 16B, XOR-swizzled
__device__ __forceinline__ uint32_t swz64(uint32_t row, uint32_t kc) {
    return row * 128 + ((kc ^ (row & 7)) * 16);
}

// ---------------- token-shift mixing -> split fp16 ----------------
__global__ void mix_kernel(const float* __restrict__ x, const float* __restrict__ state,
                           const float* __restrict__ tmk, const float* __restrict__ tmv,
                           const float* __restrict__ tmr, const float* __restrict__ tmg)
{
    int idx = blockIdx.x * 256 + threadIdx.x;
    if (idx >= NTOT) return;
    int c = idx & (C_ - 1);
    int t = (idx >> 11) & (T_ - 1);
    float xc = x[idx];
    float xp = (t == 0) ? state[c] : x[idx - C_];
    float mk = tmk[c], mv = tmv[c], mr = tmr[c], mg = tmg[c];
    float vk = xc * mk + xp * (1.f - mk);
    float vv = xc * mv + xp * (1.f - mv);
    float vr = xc * mr + xp * (1.f - mr);
    float vg = xc * mg + xp * (1.f - mg);
    __half h;
    h = __float2half(vk); g_xkh[idx] = h; g_xkl[idx] = __float2half(vk - __half2float(h));
    h = __float2half(vv); g_xvh[idx] = h; g_xvl[idx] = __float2half(vv - __half2float(h));
    h = __float2half(vr); g_xrh[idx] = h; g_xrl[idx] = __float2half(vr - __half2float(h));
    g_xgh[idx] = __float2half(vg);
}

// ---------------- fp32 -> split fp16 weight conversion (all 5 in one launch) ------------
__global__ void wconv5_kernel(const float* __restrict__ w0, const float* __restrict__ w1,
                              const float* __restrict__ w2, const float* __restrict__ w3,
                              const float* __restrict__ w4)
{
    int idx = blockIdx.x * 256 + threadIdx.x;
    if (idx >= WSZ) return;
    const float* src;
    __half *dh, *dl;
    switch (blockIdx.y) {
        case 0: src = w0; dh = g_wrh; dl = g_wrl; break;
        case 1: src = w1; dh = g_wkh; dl = g_wkl; break;
        case 2: src = w2; dh = g_wvh; dl = g_wvl; break;
        case 3: src = w3; dh = g_wgh; dl = g_wgl; break;
        default: src = w4; dh = g_woh; dl = g_wol; break;
    }
    float v = src[idx];
    __half h = __float2half(v);
    dh[idx] = h;
    dl[idx] = __float2half(v - __half2float(h));
}

// ======== fused projection GEMM: z=0..2 -> r/k/v (3-term), z=3 -> g (2-term + silu) ========
// CTA 128x128, BK=64, NSTAGE=3, 8 warps (4m x 2n), warp tile 32x64.
#define NSTAGE3 3
#define STG3 65536    /* Ah 16K + Al 16K + Bh 16K + Bl 16K */
__launch_bounds__(256)
__global__ void hgemm4x(float* __restrict__ C0, float* __restrict__ C1,
                        float* __restrict__ C2, float* __restrict__ C3)
{
    extern __shared__ __align__(128) char smem[];
    const uint32_t sb = smem_u32(smem);
    const int tid = threadIdx.x;
    const int wid = tid >> 5;
    const int lid = tid & 31;
    const int warp_m = wid >> 1;
    const int warp_n = wid & 1;
    const int bm = blockIdx.y * 128, bn = blockIdx.x * 128;
    const int mat = blockIdx.z;
    const bool three = (mat < 3);

    const __half* Ah = (mat == 0) ? g_xrh : (mat == 1) ? g_xkh : (mat == 2) ? g_xvh : g_xgh;
    const __half* Al = (mat == 0) ? g_xrl : (mat == 1) ? g_xkl : g_xvl;  // unused for mat 3
    const __half* Bh = (mat == 0) ? g_wrh : (mat == 1) ? g_wkh : (mat == 2) ? g_wvh : g_wgh;
    const __half* Bl = (mat == 0) ? g_wrl : (mat == 1) ? g_wkl : (mat == 2) ? g_wvl : g_wgl;
    float* Cmat = (mat == 0) ? C0 : (mat == 1) ? C1 : (mat == 2) ? C2 : C3;

    const __half* mats[4] = { Ah, Al, Bh, Bl };
    const int rbase[4] = { bm, bm, bn, bn };

    auto load_stage = [&](int s, int p) {
        const int k0 = s * 64;
        const uint32_t sbase = sb + p * STG3;
#pragma unroll
        for (int m = 0; m < 4; m++) {
            if (m == 1 && !three) continue;   // no A-low for g
            const __half* src = mats[m] + (size_t)rbase[m] * C_ + k0;
            const uint32_t tb = sbase + m * 16384;
#pragma unroll
            for (int i = 0; i < 4; i++) {
                int chunk = tid + 256 * i;
                int row = chunk >> 3, kc = chunk & 7;
                CPASYNC16(tb + swz64(row, kc), (const char*)(src + (size_t)row * C_) + kc * 16);
            }
        }
    };

    float acc[2][8][4];
#pragma unroll
    for (int mb = 0; mb < 2; mb++)
#pragma unroll
        for (int nf = 0; nf < 8; nf++)
#pragma unroll
            for (int q = 0; q < 4; q++) acc[mb][nf][q] = 0.f;

    load_stage(0, 0); CPCOMMIT();
    load_stage(1, 1); CPCOMMIT();

    const int KS = C_ / 64;
    const uint32_t a_row = lid & 15;
    const uint32_t a_kc  = lid >> 4;
    const uint32_t b_row = (lid & 7) + ((lid >> 4) & 1) * 8;
    const uint32_t b_kc  = (lid >> 3) & 1;

    for (int ks = 0; ks < KS; ks++) {
        CPWAIT1();
        __syncthreads();
        if (ks + 2 < KS) load_stage(ks + 2, (ks + 2) % NSTAGE3);
        CPCOMMIT();

        const uint32_t sbase = sb + (ks % NSTAGE3) * STG3;
#pragma unroll
        for (int kk = 0; kk < 4; kk++) {
            uint32_t ah[2][4], al[2][4];
#pragma unroll
            for (int mb = 0; mb < 2; mb++) {
                uint32_t row = warp_m * 32 + mb * 16 + a_row;
                uint32_t off = swz64(row, kk * 2 + a_kc);
                ldsm_x4(ah[mb], sbase + off);
                if (three) ldsm_x4(al[mb], sbase + 16384 + off);
            }
            uint32_t bh[8][2], bl[8][2];
#pragma unroll
            for (int nb = 0; nb < 4; nb++) {
                uint32_t row = warp_n * 64 + nb * 16 + b_row;
                uint32_t off = swz64(row, kk * 2 + b_kc);
                uint32_t t[4];
                ldsm_x4(t, sbase + 32768 + off);
                bh[nb * 2][0] = t[0]; bh[nb * 2][1] = t[1];
                bh[nb * 2 + 1][0] = t[2]; bh[nb * 2 + 1][1] = t[3];
                ldsm_x4(t, sbase + 49152 + off);
                bl[nb * 2][0] = t[0]; bl[nb * 2][1] = t[1];
                bl[nb * 2 + 1][0] = t[2]; bl[nb * 2 + 1][1] = t[3];
            }
#pragma unroll
            for (int mb = 0; mb < 2; mb++)
#pragma unroll
                for (int nf = 0; nf < 8; nf++) {
                    mma_f16(acc[mb][nf], ah[mb], bh[nf]);
                    mma_f16(acc[mb][nf], ah[mb], bl[nf]);
                    if (three) mma_f16(acc[mb][nf], al[mb], bh[nf]);
                }
        }
    }
    CPWAIT0();

#pragma unroll
    for (int mb = 0; mb < 2; mb++) {
        int r0 = bm + warp_m * 32 + mb * 16 + (lid >> 2);
#pragma unroll
        for (int nf = 0; nf < 8; nf++) {
            int cc = bn + warp_n * 64 + nf * 8 + (lid & 3) * 2;
            float v0 = acc[mb][nf][0], v1 = acc[mb][nf][1];
            float v2 = acc[mb][nf][2], v3 = acc[mb][nf][3];
            if (!three) {
                v0 = v0 / (1.f + expf(-v0)); v1 = v1 / (1.f + expf(-v1));
                v2 = v2 / (1.f + expf(-v2)); v3 = v3 / (1.f + expf(-v3));
            }
            *(float2*)&Cmat[(size_t)r0 * C_ + cc] = make_float2(v0, v1);
            *(float2*)&Cmat[(size_t)(r0 + 8) * C_ + cc] = make_float2(v2, v3);
        }
    }
}

// ======== 2-term HMMA GEMM (w_o): C = Ah*Bh + Ah*Bl ========
#define STG2 49152
__launch_bounds__(256)
__global__ void hgemm2o(const __half* __restrict__ Ah,
                        const __half* __restrict__ Bh, const __half* __restrict__ Bl,
                        float* __restrict__ Cmat)
{
    extern __shared__ __align__(128) char smem[];
    const uint32_t sb = smem_u32(smem);
    const int tid = threadIdx.x;
    const int wid = tid >> 5;
    const int lid = tid & 31;
    const int warp_m = wid >> 1;
    const int warp_n = wid & 1;
    const int bm = blockIdx.y * 128, bn = blockIdx.x * 128;

    const __half* mats[3] = { Ah, Bh, Bl };
    const int rbase[3] = { bm, bn, bn };

    auto load_stage = [&](int s, int p) {
        const int k0 = s * 64;
        const uint32_t sbase = sb + p * STG2;
#pragma unroll
        for (int m = 0; m < 3; m++) {
            const __half* src = mats[m] + (size_t)rbase[m] * C_ + k0;
            const uint32_t tb = sbase + m * 16384;
#pragma unroll
            for (int i = 0; i < 4; i++) {
                int chunk = tid + 256 * i;
                int row = chunk >> 3, kc = chunk & 7;
                CPASYNC16(tb + swz64(row, kc), (const char*)(src + (size_t)row * C_) + kc * 16);
            }
        }
    };

    float acc[2][8][4];
#pragma unroll
    for (int mb = 0; mb < 2; mb++)
#pragma unroll
        for (int nf = 0; nf < 8; nf++)
#pragma unroll
            for (int q = 0; q < 4; q++) acc[mb][nf][q] = 0.f;

    load_stage(0, 0); CPCOMMIT();
    load_stage(1, 1); CPCOMMIT();

    const int KS = C_ / 64;
    const uint32_t a_row = lid & 15;
    const uint32_t a_kc  = lid >> 4;
    const uint32_t b_row = (lid & 7) + ((lid >> 4) & 1) * 8;
    const uint32_t b_kc  = (lid >> 3) & 1;

    for (int ks = 0; ks < KS; ks++) {
        CPWAIT1();
        __syncthreads();
        if (ks + 2 < KS) load_stage(ks + 2, (ks + 2) % NSTAGE3);
        CPCOMMIT();

        const uint32_t sbase = sb + (ks % NSTAGE3) * STG2;
#pragma unroll
        for (int kk = 0; kk < 4; kk++) {
            uint32_t ah[2][4];
#pragma unroll
            for (int mb = 0; mb < 2; mb++) {
                uint32_t row = warp_m * 32 + mb * 16 + a_row;
                ldsm_x4(ah[mb], sbase + swz64(row, kk * 2 + a_kc));
            }
            uint32_t bh[8][2], bl[8][2];
#pragma unroll
            for (int nb = 0; nb < 4; nb++) {
                uint32_t row = warp_n * 64 + nb * 16 + b_row;
                uint32_t off = swz64(row, kk * 2 + b_kc);
                uint32_t t[4];
                ldsm_x4(t, sbase + 16384 + off);
                bh[nb * 2][0] = t[0]; bh[nb * 2][1] = t[1];
                bh[nb * 2 + 1][0] = t[2]; bh[nb * 2 + 1][1] = t[3];
                ldsm_x4(t, sbase + 32768 + off);
                bl[nb * 2][0] = t[0]; bl[nb * 2][1] = t[1];
                bl[nb * 2 + 1][0] = t[2]; bl[nb * 2 + 1][1] = t[3];
            }
#pragma unroll
            for (int mb = 0; mb < 2; mb++)
#pragma unroll
                for (int nf = 0; nf < 8; nf++) {
                    mma_f16(acc[mb][nf], ah[mb], bh[nf]);
                    mma_f16(acc[mb][nf], ah[mb], bl[nf]);
                }
        }
    }
    CPWAIT0();

#pragma unroll
    for (int mb = 0; mb < 2; mb++) {
        int r0 = bm + warp_m * 32 + mb * 16 + (lid >> 2);
#pragma unroll
        for (int nf = 0; nf < 8; nf++) {
            int cc = bn + warp_n * 64 + nf * 8 + (lid & 3) * 2;
            *(float2*)&Cmat[(size_t)r0 * C_ + cc] = make_float2(acc[mb][nf][0], acc[mb][nf][1]);
            *(float2*)&Cmat[(size_t)(r0 + 8) * C_ + cc] = make_float2(acc[mb][nf][2], acc[mb][nf][3]);
        }
    }
}

// ============ wkv phase 1 (triangular-skipped) ============
__global__ void wkv_p1(const float* __restrict__ wkvstate,
                       const float* __restrict__ time_decay,
                       const float* __restrict__ time_faaaa)
{
    extern __shared__ float sm[];
    float (*Rs)[PCH] = (float (*)[PCH])(sm);
    float (*Ks)[PCH] = (float (*)[PCH])(sm + 1 * 64 * PCH);
    float (*Vs)[PCH] = (float (*)[PCH])(sm + 2 * 64 * PCH);
    float (*Am)[PCH] = (float (*)[PCH])(sm + 3 * 64 * PCH);
    float (*WF)[PCH] = (float (*)[PCH])(sm + 4 * 64 * PCH);
    float (*Ws)[PCH] = (float (*)[PCH])(sm + 5 * 64 * PCH);
    __shared__ float ew[64], uu[64], bonus[64];

    const int gid = blockIdx.x;
    const int bh = gid >> 5, ck = gid & 31;
    const int b = bh >> 5, h = bh & 31;
    const int tid = threadIdx.x;
    const int row = tid & 63, jg = tid >> 6, j0 = jg * 16;

    if (tid < 64) {
        ew[tid] = expf(time_decay[h * 64 + tid]);
        uu[tid] = time_faaaa[h * 64 + tid];
    }
    const float* W0 = wkvstate + h * 64 * 64;
#pragma unroll
    for (int j = 0; j < 16; j++) Ws[row][j0 + j] = W0[row * 64 + j0 + j];

    const int t0 = ck * 64;
    const int off = (b * T_) * C_ + h * 64 + (t0 + row) * C_ + j0;
#pragma unroll
    for (int j4 = 0; j4 < 4; j4++) {
        int jj = j0 + 4 * j4;
        *(float4*)&Rs[row][jj] = *(const float4*)&g_r[off + 4 * j4];
        *(float4*)&Ks[row][jj] = *(const float4*)&g_k[off + 4 * j4];
        *(float4*)&Vs[row][jj] = *(const float4*)&g_v[off + 4 * j4];
    }
    __syncthreads();

    {
        float tg = (float)(t0 + row);
#pragma unroll
        for (int j = 0; j < 16; j++)
            WF[row][j0 + j] = Rs[row][j0 + j] * expf(-tg * ew[j0 + j]);
    }
    if (tid < 64) {
        float s = 0.f;
        for (int kk = 0; kk < 64; kk += 4) {
            float4 rv = *(const float4*)&Rs[tid][kk];
            float4 kv = *(const float4*)&Ks[tid][kk];
            float4 uv = *(const float4*)&uu[kk];
            s += rv.x * kv.x * uv.x + rv.y * kv.y * uv.y + rv.z * kv.z * uv.z + rv.w * kv.w * uv.w;
        }
        bonus[tid] = s;
    }
    __syncthreads();

    {
        float qb = (float)(T_ - 1 - (t0 + row));
#pragma unroll
        for (int j = 0; j < 16; j++)
            Ks[row][j0 + j] *= expf(-qb * ew[j0 + j]);
    }
    __syncthreads();

    // G = K2^T V
    {
        float ga[16];
#pragma unroll
        for (int j = 0; j < 16; j++) ga[j] = 0.f;
        for (int q = 0; q < 64; q++) {
            float kv = Ks[q][row];
#pragma unroll
            for (int j4 = 0; j4 < 4; j4++) {
                float4 vv = *(const float4*)&Vs[q][j0 + 4 * j4];
                ga[4 * j4 + 0] += kv * vv.x; ga[4 * j4 + 1] += kv * vv.y;
                ga[4 * j4 + 2] += kv * vv.z; ga[4 * j4 + 3] += kv * vv.w;
            }
        }
        float* gp = g_S + (size_t)gid * 4096 + row * 64 + j0;
#pragma unroll
        for (int j4 = 0; j4 < 4; j4++)
            *(float4*)&gp[4 * j4] = make_float4(ga[4 * j4], ga[4 * j4 + 1], ga[4 * j4 + 2], ga[4 * j4 + 3]);
    }

    // A = R K2^T, strict lower mask. Warp-level skip when entire block above diagonal:
    // warp rows span [wr0, wr0+31]; if j0 >= wr0+31 no (row,j0+j<row) possible -> zeros only.
    {
        const int wr0 = (tid & 32) ? 32 : 0;   // warp's min row (rows are 32-consecutive)
        const bool skip = (j0 >= wr0 + 31);
        float a[16];
#pragma unroll
        for (int j = 0; j < 16; j++) a[j] = 0.f;
        if (!skip) {
            for (int kk = 0; kk < 64; kk += 4) {
                float4 rv = *(const float4*)&Rs[row][kk];
#pragma unroll
                for (int j = 0; j < 16; j++) {
                    float4 kv = *(const float4*)&Ks[j0 + j][kk];
                    a[j] += rv.x * kv.x + rv.y * kv.y + rv.z * kv.z + rv.w * kv.w;
                }
            }
        }
#pragma unroll
        for (int j = 0; j < 16; j++)
            Am[row][j0 + j] = (j0 + j < row) ? a[j] : 0.f;
    }
    __syncthreads();

    // P = A V (q < row only; Am zero beyond) + bonus*v + WF @ W0
    {
        float o[16];
#pragma unroll
        for (int j = 0; j < 16; j++) o[j] = 0.f;
        for (int q = 0; q < row; q++) {
            float av = Am[row][q];
#pragma unroll
            for (int j4 = 0; j4 < 4; j4++) {
                float4 vv = *(const float4*)&Vs[q][j0 + 4 * j4];
                o[4 * j4 + 0] += av * vv.x; o[4 * j4 + 1] += av * vv.y;
                o[4 * j4 + 2] += av * vv.z; o[4 * j4 + 3] += av * vv.w;
            }
        }
        {
            float bb = bonus[row];
#pragma unroll
            for (int j4 = 0; j4 < 4; j4++) {
                float4 vv = *(const float4*)&Vs[row][j0 + 4 * j4];
                o[4 * j4 + 0] += bb * vv.x; o[4 * j4 + 1] += bb * vv.y;
                o[4 * j4 + 2] += bb * vv.z; o[4 * j4 + 3] += bb * vv.w;
            }
        }
        for (int kk = 0; kk < 64; kk++) {
            float rw = WF[row][kk];
#pragma unroll
            for (int j4 = 0; j4 < 4; j4++) {
                float4 wv = *(const float4*)&Ws[kk][j0 + 4 * j4];
                o[4 * j4 + 0] += rw * wv.x; o[4 * j4 + 1] += rw * wv.y;
                o[4 * j4 + 2] += rw * wv.z; o[4 * j4 + 3] += rw * wv.w;
            }
        }
        float* pp = g_po + (size_t)gid * 4096 + row * 64 + j0;
#pragma unroll
        for (int j4 = 0; j4 < 4; j4++)
            *(float4*)&pp[4 * j4] = make_float4(o[4 * j4], o[4 * j4 + 1], o[4 * j4 + 2], o[4 * j4 + 3]);
    }
}

// ============ wkv phase 2: exclusive prefix of G over chunks (per bh) ============
__global__ void wkv_p2()
{
    const int bh = blockIdx.x;
    const int e = threadIdx.x * 16;
    float run[16];
#pragma unroll
    for (int j = 0; j < 16; j++) run[j] = 0.f;
    for (int ck = 0; ck < 32; ck++) {
        float* p = g_S + (size_t)(bh * 32 + ck) * 4096 + e;
        float t[16];
#pragma unroll
        for (int j4 = 0; j4 < 4; j4++) {
            float4 v = *(const float4*)&p[4 * j4];
            t[4 * j4] = v.x; t[4 * j4 + 1] = v.y; t[4 * j4 + 2] = v.z; t[4 * j4 + 3] = v.w;
        }
#pragma unroll
        for (int j4 = 0; j4 < 4; j4++) {
            float4 v = make_float4(run[4 * j4], run[4 * j4 + 1], run[4 * j4 + 2], run[4 * j4 + 3]);
            *(float4*)&p[4 * j4] = v;
        }
#pragma unroll
        for (int j = 0; j < 16; j++) run[j] += t[j];
    }
}

// ============ wkv phase 3: o = P + R@S_c, then bf16-cast + groupnorm + gate ============
__global__ void wkv_p3(const float* __restrict__ lnw, const float* __restrict__ lnb)
{
    extern __shared__ float sm[];
    float (*Rs)[PCH] = (float (*)[PCH])(sm);
    float (*Ss)[PCH] = (float (*)[PCH])(sm + 1 * 64 * PCH);
    float (*Am)[PCH] = (float (*)[PCH])(sm + 2 * 64 * PCH);
    __shared__ float mu_s[64], rstd_s[64], lw_s[64], lb_s[64];

    const int gid = blockIdx.x;
    const int bh = gid >> 5, ck = gid & 31;
    const int b = bh >> 5, h = bh & 31;
    const int tid = threadIdx.x;
    const int row = tid & 63, jg = tid >> 6, j0 = jg * 16;

    if (tid < 64) {
        lw_s[tid] = lnw[h * 64 + tid];
        lb_s[tid] = lnb[h * 64 + tid];
    }
    const int t0 = ck * 64;
    const int off = (b * T_) * C_ + h * 64 + (t0 + row) * C_ + j0;

#pragma unroll
    for (int j4 = 0; j4 < 4; j4++) {
        int jj = j0 + 4 * j4;
        *(float4*)&Rs[row][jj] = *(const float4*)&g_r[off + 4 * j4];
        *(float4*)&Ss[row][jj] = *(const float4*)&g_S[(size_t)gid * 4096 + row * 64 + jj];
    }
    float o[16];
    {
        const float* pp = g_po + (size_t)gid * 4096 + row * 64 + j0;
#pragma unroll
        for (int j4 = 0; j4 < 4; j4++) {
            float4 v = *(const float4*)&pp[4 * j4];
            o[4 * j4] = v.x; o[4 * j4 + 1] = v.y; o[4 * j4 + 2] = v.z; o[4 * j4 + 3] = v.w;
        }
    }
    __syncthreads();

    for (int kk = 0; kk < 64; kk++) {
        float rv = Rs[row][kk];
#pragma unroll
        for (int j4 = 0; j4 < 4; j4++) {
            float4 sv = *(const float4*)&Ss[kk][j0 + 4 * j4];
            o[4 * j4 + 0] += rv * sv.x; o[4 * j4 + 1] += rv * sv.y;
            o[4 * j4 + 2] += rv * sv.z; o[4 * j4 + 3] += rv * sv.w;
        }
    }

#pragma unroll
    for (int j = 0; j < 16; j++)
        Am[row][j0 + j] = __bfloat162float(__float2bfloat16(o[j]));
    __syncthreads();

    if (tid < 64) {
        float m = 0.f;
        for (int j = 0; j < 64; j++) m += Am[tid][j];
        m *= (1.f / 64.f);
        float v2 = 0.f;
        for (int j = 0; j < 64; j++) { float d = Am[tid][j] - m; v2 += d * d; }
        v2 *= (1.f / 64.f);
        mu_s[tid] = m;
        rstd_s[tid] = 1.f / sqrtf(v2 + EPS_);
    }
    __syncthreads();

    {
        float m = mu_s[row], rs = rstd_s[row];
#pragma unroll
        for (int j = 0; j < 16; j++) {
            float y = (Am[row][j0 + j] - m) * rs * lw_s[j0 + j] + lb_s[j0 + j];
            float z = y * g_gt[off + j];
            g_zh[off + j] = __float2half(z);
        }
    }
}

// ---------------- launch ----------------
extern "C" void kernel_launch(void* const* d_in, const int* in_sizes, int n_in,
                              void* d_out, int out_size)
{
    const float* x     = (const float*)d_in[0];
    const float* state = (const float*)d_in[1];
    const float* wkvs  = (const float*)d_in[2];
    const float* tmk   = (const float*)d_in[3];
    const float* tmv   = (const float*)d_in[4];
    const float* tmr   = (const float*)d_in[5];
    const float* tmg   = (const float*)d_in[6];
    const float* tdec  = (const float*)d_in[7];
    const float* tfaa  = (const float*)d_in[8];
    const float* w_r   = (const float*)d_in[9];
    const float* w_k   = (const float*)d_in[10];
    const float* w_v   = (const float*)d_in[11];
    const float* w_g   = (const float*)d_in[12];
    const float* w_o   = (const float*)d_in[13];
    const float* lnw   = (const float*)d_in[14];
    const float* lnb   = (const float*)d_in[15];

    __half *zh, *woh, *wol;
    float *pr, *pk, *pv, *pg;
    cudaGetSymbolAddress((void**)&zh,  g_zh);
    cudaGetSymbolAddress((void**)&woh, g_woh); cudaGetSymbolAddress((void**)&wol, g_wol);
    cudaGetSymbolAddress((void**)&pr,  g_r);   cudaGetSymbolAddress((void**)&pk,  g_k);
    cudaGetSymbolAddress((void**)&pv,  g_v);   cudaGetSymbolAddress((void**)&pg,  g_gt);

    mix_kernel<<<(NTOT + 255) / 256, 256>>>(x, state, tmk, tmv, tmr, tmg);
    {
        dim3 wgrid((WSZ + 255) / 256, 5);
        wconv5_kernel<<<wgrid, 256>>>(w_r, w_k, w_v, w_g, w_o);
    }

    const int gsm3 = NSTAGE3 * STG3;   // 192KB
    const int gsm2 = NSTAGE3 * STG2;   // 144KB
    cudaFuncSetAttribute(hgemm4x, cudaFuncAttributeMaxDynamicSharedMemorySize, gsm3);
    cudaFuncSetAttribute(hgemm2o, cudaFuncAttributeMaxDynamicSharedMemorySize, gsm2);

    dim3 gg(C_ / 128, M_ / 128);
    dim3 gg4(C_ / 128, M_ / 128, 4);
    hgemm4x<<<gg4, 256, gsm3>>>(pr, pk, pv, pg);

    const int p1sm = 6 * 64 * PCH * 4;
    const int p3sm = 3 * 64 * PCH * 4;
    cudaFuncSetAttribute(wkv_p1, cudaFuncAttributeMaxDynamicSharedMemorySize, p1sm);
    cudaFuncSetAttribute(wkv_p3, cudaFuncAttributeMaxDynamicSharedMemorySize, p3sm);
    wkv_p1<<<128 * 32, 256, p1sm>>>(wkvs, tdec, tfaa);
    wkv_p2<<<128, 256>>>();
    wkv_p3<<<128 * 32, 256, p3sm>>>(lnw, lnb);

    hgemm2o<<<gg, 256, gsm2>>>(zh, woh, wol, (float*)d_out);
}

// round 14
// speedup vs baseline: 1.0608x; 1.0608x over previous
#include <cuda_runtime.h>
#include <cuda_fp16.h>
#include <cuda_bf16.h>
#include <cstdint>

#define B_ 4
#define T_ 2048
#define C_ 2048
#define H_ 32
#define M_ (B_*T_)
#define NTOT (M_*C_)
#define WSZ (C_*C_)
#define EPS_ 0.00064f
#define PCH 68

// ---------------- scratch (static device globals; allocation-free) ----------------
__device__ __half g_xrh[NTOT], g_xrl[NTOT];
__device__ __half g_xkh[NTOT], g_xkl[NTOT];
__device__ __half g_xvh[NTOT], g_xvl[NTOT];
__device__ __half g_xgh[NTOT];
__device__ __half g_zh[NTOT];
__device__ float g_r[NTOT], g_k[NTOT], g_v[NTOT], g_gt[NTOT];
__device__ float g_S[128 * 32 * 4096];
__device__ float g_po[128 * 32 * 4096];
__device__ __half g_wrh[WSZ], g_wrl[WSZ];
__device__ __half g_wkh[WSZ], g_wkl[WSZ];
__device__ __half g_wvh[WSZ], g_wvl[WSZ];
__device__ __half g_wgh[WSZ], g_wgl[WSZ];
__device__ __half g_woh[WSZ], g_wol[WSZ];

// ---------------- PTX helpers (baseline PTX only) ----------------
__device__ __forceinline__ uint32_t smem_u32(const void* p) {
    uint32_t a;
    asm("{ .reg .u64 t; cvta.to.shared.u64 t, %1; cvt.u32.u64 %0, t; }" : "=r"(a) : "l"(p));
    return a;
}
#define CPASYNC16(dst, src) \
    asm volatile("cp.async.cg.shared.global [%0], [%1], 16;" :: "r"(dst), "l"(src))
#define CPCOMMIT() asm volatile("cp.async.commit_group;" ::: "memory")
#define CPWAIT1()  asm volatile("cp.async.wait_group 1;" ::: "memory")
#define CPWAIT0()  asm volatile("cp.async.wait_group 0;" ::: "memory")

__device__ __forceinline__ void ldsm_x4(uint32_t* r, uint32_t addr) {
    asm volatile("ldmatrix.sync.aligned.m8n8.x4.shared.b16 {%0,%1,%2,%3}, [%4];"
                 : "=r"(r[0]), "=r"(r[1]), "=r"(r[2]), "=r"(r[3]) : "r"(addr));
}
__device__ __forceinline__ void mma_f16(float* c, const uint32_t* a, const uint32_t* b) {
    asm volatile(
        "mma.sync.aligned.m16n8k16.row.col.f32.f16.f16.f32 "
        "{%0,%1,%2,%3}, {%4,%5,%6,%7}, {%8,%9}, {%0,%1,%2,%3};"
        : "+f"(c[0]), "+f"(c[1]), "+f"(c[2]), "+f"(c[3])
        : "r"(a[0]), "r"(a[1]), "r"(a[2]), "r"(a[3]), "r"(b[0]), "r"(b[1]));
}

// smem tile: 128 rows x 64 fp16 = 128B/row; 8 chunks of 16B, XOR-swizzled
__device__ __forceinline__ uint32_t swz64(uint32_t row, uint32_t kc) {
    return row * 128 + ((kc ^ (row & 7)) * 16);
}

// ---------------- token-shift mixing -> split fp16 ----------------
__global__ void mix_kernel(const float* __restrict__ x, const float* __restrict__ state,
                           const float* __restrict__ tmk, const float* __restrict__ tmv,
                           const float* __restrict__ tmr, const float* __restrict__ tmg)
{
    int idx = blockIdx.x * 256 + threadIdx.x;
    if (idx >= NTOT) return;
    int c = idx & (C_ - 1);
    int t = (idx >> 11) & (T_ - 1);
    float xc = x[idx];
    float xp = (t == 0) ? state[c] : x[idx - C_];
    float mk = tmk[c], mv = tmv[c], mr = tmr[c], mg = tmg[c];
    float vk = xc * mk + xp * (1.f - mk);
    float vv = xc * mv + xp * (1.f - mv);
    float vr = xc * mr + xp * (1.f - mr);
    float vg = xc * mg + xp * (1.f - mg);
    __half h;
    h = __float2half(vk); g_xkh[idx] = h; g_xkl[idx] = __float2half(vk - __half2float(h));
    h = __float2half(vv); g_xvh[idx] = h; g_xvl[idx] = __float2half(vv - __half2float(h));
    h = __float2half(vr); g_xrh[idx] = h; g_xrl[idx] = __float2half(vr - __half2float(h));
    g_xgh[idx] = __float2half(vg);
}

// ---------------- fp32 -> split fp16 weight conversion (all 5 in one launch) ------------
__global__ void wconv5_kernel(const float* __restrict__ w0, const float* __restrict__ w1,
                              const float* __restrict__ w2, const float* __restrict__ w3,
                              const float* __restrict__ w4)
{
    int idx = blockIdx.x * 256 + threadIdx.x;
    if (idx >= WSZ) return;
    const float* src;
    __half *dh, *dl;
    switch (blockIdx.y) {
        case 0: src = w0; dh = g_wrh; dl = g_wrl; break;
        case 1: src = w1; dh = g_wkh; dl = g_wkl; break;
        case 2: src = w2; dh = g_wvh; dl = g_wvl; break;
        case 3: src = w3; dh = g_wgh; dl = g_wgl; break;
        default: src = w4; dh = g_woh; dl = g_wol; break;
    }
    float v = src[idx];
    __half h = __float2half(v);
    dh[idx] = h;
    dl[idx] = __float2half(v - __half2float(h));
}

// ======== 3-term HMMA GEMM (r,k,v fused via blockIdx.z) — R10-proven ========
#define NSTAGE3 3
#define STG3 65536
__launch_bounds__(256)
__global__ void hgemm3x(float* __restrict__ C0, float* __restrict__ C1, float* __restrict__ C2)
{
    extern __shared__ __align__(128) char smem[];
    const uint32_t sb = smem_u32(smem);
    const int tid = threadIdx.x;
    const int wid = tid >> 5;
    const int lid = tid & 31;
    const int warp_m = wid >> 1;
    const int warp_n = wid & 1;
    const int bm = blockIdx.y * 128, bn = blockIdx.x * 128;
    const int mat = blockIdx.z;

    const __half* Ah = (mat == 0) ? g_xrh : (mat == 1) ? g_xkh : g_xvh;
    const __half* Al = (mat == 0) ? g_xrl : (mat == 1) ? g_xkl : g_xvl;
    const __half* Bh = (mat == 0) ? g_wrh : (mat == 1) ? g_wkh : g_wvh;
    const __half* Bl = (mat == 0) ? g_wrl : (mat == 1) ? g_wkl : g_wvl;
    float* Cmat = (mat == 0) ? C0 : (mat == 1) ? C1 : C2;

    const __half* mats[4] = { Ah, Al, Bh, Bl };
    const int rbase[4] = { bm, bm, bn, bn };

    auto load_stage = [&](int s, int p) {
        const int k0 = s * 64;
        const uint32_t sbase = sb + p * STG3;
#pragma unroll
        for (int m = 0; m < 4; m++) {
            const __half* src = mats[m] + (size_t)rbase[m] * C_ + k0;
            const uint32_t tb = sbase + m * 16384;
#pragma unroll
            for (int i = 0; i < 4; i++) {
                int chunk = tid + 256 * i;
                int row = chunk >> 3, kc = chunk & 7;
                CPASYNC16(tb + swz64(row, kc), (const char*)(src + (size_t)row * C_) + kc * 16);
            }
        }
    };

    float acc[2][8][4];
#pragma unroll
    for (int mb = 0; mb < 2; mb++)
#pragma unroll
        for (int nf = 0; nf < 8; nf++)
#pragma unroll
            for (int q = 0; q < 4; q++) acc[mb][nf][q] = 0.f;

    load_stage(0, 0); CPCOMMIT();
    load_stage(1, 1); CPCOMMIT();

    const int KS = C_ / 64;
    const uint32_t a_row = lid & 15;
    const uint32_t a_kc  = lid >> 4;
    const uint32_t b_row = (lid & 7) + ((lid >> 4) & 1) * 8;
    const uint32_t b_kc  = (lid >> 3) & 1;

    for (int ks = 0; ks < KS; ks++) {
        CPWAIT1();
        __syncthreads();
        if (ks + 2 < KS) load_stage(ks + 2, (ks + 2) % NSTAGE3);
        CPCOMMIT();

        const uint32_t sbase = sb + (ks % NSTAGE3) * STG3;
#pragma unroll
        for (int kk = 0; kk < 4; kk++) {
            uint32_t ah[2][4], al[2][4];
#pragma unroll
            for (int mb = 0; mb < 2; mb++) {
                uint32_t row = warp_m * 32 + mb * 16 + a_row;
                uint32_t off = swz64(row, kk * 2 + a_kc);
                ldsm_x4(ah[mb], sbase + off);
                ldsm_x4(al[mb], sbase + 16384 + off);
            }
            uint32_t bh[8][2], bl[8][2];
#pragma unroll
            for (int nb = 0; nb < 4; nb++) {
                uint32_t row = warp_n * 64 + nb * 16 + b_row;
                uint32_t off = swz64(row, kk * 2 + b_kc);
                uint32_t t[4];
                ldsm_x4(t, sbase + 32768 + off);
                bh[nb * 2][0] = t[0]; bh[nb * 2][1] = t[1];
                bh[nb * 2 + 1][0] = t[2]; bh[nb * 2 + 1][1] = t[3];
                ldsm_x4(t, sbase + 49152 + off);
                bl[nb * 2][0] = t[0]; bl[nb * 2][1] = t[1];
                bl[nb * 2 + 1][0] = t[2]; bl[nb * 2 + 1][1] = t[3];
            }
#pragma unroll
            for (int mb = 0; mb < 2; mb++)
#pragma unroll
                for (int nf = 0; nf < 8; nf++) {
                    mma_f16(acc[mb][nf], ah[mb], bh[nf]);
                    mma_f16(acc[mb][nf], ah[mb], bl[nf]);
                    mma_f16(acc[mb][nf], al[mb], bh[nf]);
                }
        }
    }
    CPWAIT0();

#pragma unroll
    for (int mb = 0; mb < 2; mb++) {
        int r0 = bm + warp_m * 32 + mb * 16 + (lid >> 2);
#pragma unroll
        for (int nf = 0; nf < 8; nf++) {
            int cc = bn + warp_n * 64 + nf * 8 + (lid & 3) * 2;
            *(float2*)&Cmat[(size_t)r0 * C_ + cc] = make_float2(acc[mb][nf][0], acc[mb][nf][1]);
            *(float2*)&Cmat[(size_t)(r0 + 8) * C_ + cc] = make_float2(acc[mb][nf][2], acc[mb][nf][3]);
        }
    }
}

// ======== 2-term HMMA GEMM (g / w_o): C = Ah*Bh + Ah*Bl — R10-proven ========
#define STG2 49152
template<int ACT>
__launch_bounds__(256)
__global__ void hgemm2(const __half* __restrict__ Ah,
                       const __half* __restrict__ Bh, const __half* __restrict__ Bl,
                       float* __restrict__ Cmat)
{
    extern __shared__ __align__(128) char smem[];
    const uint32_t sb = smem_u32(smem);
    const int tid = threadIdx.x;
    const int wid = tid >> 5;
    const int lid = tid & 31;
    const int warp_m = wid >> 1;
    const int warp_n = wid & 1;
    const int bm = blockIdx.y * 128, bn = blockIdx.x * 128;

    const __half* mats[3] = { Ah, Bh, Bl };
    const int rbase[3] = { bm, bn, bn };

    auto load_stage = [&](int s, int p) {
        const int k0 = s * 64;
        const uint32_t sbase = sb + p * STG2;
#pragma unroll
        for (int m = 0; m < 3; m++) {
            const __half* src = mats[m] + (size_t)rbase[m] * C_ + k0;
            const uint32_t tb = sbase + m * 16384;
#pragma unroll
            for (int i = 0; i < 4; i++) {
                int chunk = tid + 256 * i;
                int row = chunk >> 3, kc = chunk & 7;
                CPASYNC16(tb + swz64(row, kc), (const char*)(src + (size_t)row * C_) + kc * 16);
            }
        }
    };

    float acc[2][8][4];
#pragma unroll
    for (int mb = 0; mb < 2; mb++)
#pragma unroll
        for (int nf = 0; nf < 8; nf++)
#pragma unroll
            for (int q = 0; q < 4; q++) acc[mb][nf][q] = 0.f;

    load_stage(0, 0); CPCOMMIT();
    load_stage(1, 1); CPCOMMIT();

    const int KS = C_ / 64;
    const uint32_t a_row = lid & 15;
    const uint32_t a_kc  = lid >> 4;
    const uint32_t b_row = (lid & 7) + ((lid >> 4) & 1) * 8;
    const uint32_t b_kc  = (lid >> 3) & 1;

    for (int ks = 0; ks < KS; ks++) {
        CPWAIT1();
        __syncthreads();
        if (ks + 2 < KS) load_stage(ks + 2, (ks + 2) % NSTAGE3);
        CPCOMMIT();

        const uint32_t sbase = sb + (ks % NSTAGE3) * STG2;
#pragma unroll
        for (int kk = 0; kk < 4; kk++) {
            uint32_t ah[2][4];
#pragma unroll
            for (int mb = 0; mb < 2; mb++) {
                uint32_t row = warp_m * 32 + mb * 16 + a_row;
                ldsm_x4(ah[mb], sbase + swz64(row, kk * 2 + a_kc));
            }
            uint32_t bh[8][2], bl[8][2];
#pragma unroll
            for (int nb = 0; nb < 4; nb++) {
                uint32_t row = warp_n * 64 + nb * 16 + b_row;
                uint32_t off = swz64(row, kk * 2 + b_kc);
                uint32_t t[4];
                ldsm_x4(t, sbase + 16384 + off);
                bh[nb * 2][0] = t[0]; bh[nb * 2][1] = t[1];
                bh[nb * 2 + 1][0] = t[2]; bh[nb * 2 + 1][1] = t[3];
                ldsm_x4(t, sbase + 32768 + off);
                bl[nb * 2][0] = t[0]; bl[nb * 2][1] = t[1];
                bl[nb * 2 + 1][0] = t[2]; bl[nb * 2 + 1][1] = t[3];
            }
#pragma unroll
            for (int mb = 0; mb < 2; mb++)
#pragma unroll
                for (int nf = 0; nf < 8; nf++) {
                    mma_f16(acc[mb][nf], ah[mb], bh[nf]);
                    mma_f16(acc[mb][nf], ah[mb], bl[nf]);
                }
        }
    }
    CPWAIT0();

#pragma unroll
    for (int mb = 0; mb < 2; mb++) {
        int r0 = bm + warp_m * 32 + mb * 16 + (lid >> 2);
#pragma unroll
        for (int nf = 0; nf < 8; nf++) {
            int cc = bn + warp_n * 64 + nf * 8 + (lid & 3) * 2;
            float v0 = acc[mb][nf][0], v1 = acc[mb][nf][1];
            float v2 = acc[mb][nf][2], v3 = acc[mb][nf][3];
            if (ACT == 1) {
                v0 = v0 / (1.f + expf(-v0)); v1 = v1 / (1.f + expf(-v1));
                v2 = v2 / (1.f + expf(-v2)); v3 = v3 / (1.f + expf(-v3));
            }
            *(float2*)&Cmat[(size_t)r0 * C_ + cc] = make_float2(v0, v1);
            *(float2*)&Cmat[(size_t)(r0 + 8) * C_ + cc] = make_float2(v2, v3);
        }
    }
}

// ============ wkv phase 1: conflict-free layouts (R/WF/A stored transposed) ============
// Tiles: Rt[k][t], Ks[t][k] (pre-scaled K2), Vs[t][j], Amt[j][t], WFt[k][t], Ws[k][j].
__global__ void wkv_p1(const float* __restrict__ wkvstate,
                       const float* __restrict__ time_decay,
                       const float* __restrict__ time_faaaa)
{
    extern __shared__ float sm[];
    float (*Rt)[PCH]  = (float (*)[PCH])(sm);
    float (*Ks)[PCH]  = (float (*)[PCH])(sm + 1 * 64 * PCH);
    float (*Vs)[PCH]  = (float (*)[PCH])(sm + 2 * 64 * PCH);
    float (*Amt)[PCH] = (float (*)[PCH])(sm + 3 * 64 * PCH);
    float (*WFt)[PCH] = (float (*)[PCH])(sm + 4 * 64 * PCH);
    float (*Ws)[PCH]  = (float (*)[PCH])(sm + 5 * 64 * PCH);
    __shared__ float ew[64], uu[64], bonus[64], bpart[4][64];

    const int gid = blockIdx.x;
    const int bh = gid >> 5, ck = gid & 31;
    const int b = bh >> 5, h = bh & 31;
    const int tid = threadIdx.x;
    const int row = tid & 63, jg = tid >> 6, j0 = jg * 16;

    if (tid < 64) {
        ew[tid] = expf(time_decay[h * 64 + tid]);
        uu[tid] = time_faaaa[h * 64 + tid];
    }
    const float* W0 = wkvstate + h * 64 * 64;
#pragma unroll
    for (int j4 = 0; j4 < 4; j4++)
        *(float4*)&Ws[row][j0 + 4 * j4] = *(const float4*)&W0[row * 64 + j0 + 4 * j4];

    const int t0 = ck * 64;
    const int off = (b * T_) * C_ + h * 64 + (t0 + row) * C_ + j0;
    float4 r4[4], k4[4], v4[4];
#pragma unroll
    for (int j4 = 0; j4 < 4; j4++) {
        r4[j4] = *(const float4*)&g_r[off + 4 * j4];
        k4[j4] = *(const float4*)&g_k[off + 4 * j4];
        v4[j4] = *(const float4*)&g_v[off + 4 * j4];
        int jj = j0 + 4 * j4;
        *(float4*)&Vs[row][jj] = v4[j4];
        Rt[jj + 0][row] = r4[j4].x; Rt[jj + 1][row] = r4[j4].y;
        Rt[jj + 2][row] = r4[j4].z; Rt[jj + 3][row] = r4[j4].w;
    }
    __syncthreads();

    // WFt = (r * w^t)^T ; Ks = k * w^(T-1-q) (pre-scaled); bonus partials with raw k
    {
        float tg = (float)(t0 + row);
        float qb = (float)(T_ - 1 - (t0 + row));
        float bp = 0.f;
#pragma unroll
        for (int j4 = 0; j4 < 4; j4++) {
            int jj = j0 + 4 * j4;
            WFt[jj + 0][row] = r4[j4].x * expf(-tg * ew[jj + 0]);
            WFt[jj + 1][row] = r4[j4].y * expf(-tg * ew[jj + 1]);
            WFt[jj + 2][row] = r4[j4].z * expf(-tg * ew[jj + 2]);
            WFt[jj + 3][row] = r4[j4].w * expf(-tg * ew[jj + 3]);
            bp += r4[j4].x * k4[j4].x * uu[jj + 0] + r4[j4].y * k4[j4].y * uu[jj + 1]
                + r4[j4].z * k4[j4].z * uu[jj + 2] + r4[j4].w * k4[j4].w * uu[jj + 3];
            float4 k2;
            k2.x = k4[j4].x * expf(-qb * ew[jj + 0]);
            k2.y = k4[j4].y * expf(-qb * ew[jj + 1]);
            k2.z = k4[j4].z * expf(-qb * ew[jj + 2]);
            k2.w = k4[j4].w * expf(-qb * ew[jj + 3]);
            *(float4*)&Ks[row][jj] = k2;
        }
        bpart[jg][row] = bp;
    }
    __syncthreads();

    if (tid < 64)
        bonus[tid] = bpart[0][tid] + bpart[1][tid] + bpart[2][tid] + bpart[3][tid];

    // G = K2^T V  (row = k-index): Ks[q][row] consecutive, Vs broadcast
    {
        float ga[16];
#pragma unroll
        for (int j = 0; j < 16; j++) ga[j] = 0.f;
        for (int q = 0; q < 64; q++) {
            float kv = Ks[q][row];
#pragma unroll
            for (int j4 = 0; j4 < 4; j4++) {
                float4 vv = *(const float4*)&Vs[q][j0 + 4 * j4];
                ga[4 * j4 + 0] += kv * vv.x; ga[4 * j4 + 1] += kv * vv.y;
                ga[4 * j4 + 2] += kv * vv.z; ga[4 * j4 + 3] += kv * vv.w;
            }
        }
        float* gp = g_S + (size_t)gid * 4096 + row * 64 + j0;
#pragma unroll
        for (int j4 = 0; j4 < 4; j4++)
            *(float4*)&gp[4 * j4] = make_float4(ga[4 * j4], ga[4 * j4 + 1], ga[4 * j4 + 2], ga[4 * j4 + 3]);
    }

    // A = R K2^T (strict lower); Rt reads conflict-free, Ks broadcast float4 over kk
    {
        float a[16];
#pragma unroll
        for (int j = 0; j < 16; j++) a[j] = 0.f;
        for (int kb = 0; kb < 64; kb += 4) {
            float r0v = Rt[kb + 0][row], r1v = Rt[kb + 1][row];
            float r2v = Rt[kb + 2][row], r3v = Rt[kb + 3][row];
#pragma unroll
            for (int j = 0; j < 16; j++) {
                float4 kv = *(const float4*)&Ks[j0 + j][kb];
                a[j] += r0v * kv.x + r1v * kv.y + r2v * kv.z + r3v * kv.w;
            }
        }
#pragma unroll
        for (int j = 0; j < 16; j++)
            Amt[j0 + j][row] = (j0 + j < row) ? a[j] : 0.f;
    }
    __syncthreads();

    // P = A V + bonus*v + WF @ W0; Amt/WFt reads conflict-free, Vs/Ws broadcast
    {
        float o[16];
#pragma unroll
        for (int j = 0; j < 16; j++) o[j] = 0.f;
        for (int q = 0; q < 64; q++) {
            float av = Amt[q][row];
#pragma unroll
            for (int j4 = 0; j4 < 4; j4++) {
                float4 vv = *(const float4*)&Vs[q][j0 + 4 * j4];
                o[4 * j4 + 0] += av * vv.x; o[4 * j4 + 1] += av * vv.y;
                o[4 * j4 + 2] += av * vv.z; o[4 * j4 + 3] += av * vv.w;
            }
        }
        {
            float bb = bonus[row];
#pragma unroll
            for (int j4 = 0; j4 < 4; j4++) {
                o[4 * j4 + 0] += bb * v4[j4].x; o[4 * j4 + 1] += bb * v4[j4].y;
                o[4 * j4 + 2] += bb * v4[j4].z; o[4 * j4 + 3] += bb * v4[j4].w;
            }
        }
        for (int kk = 0; kk < 64; kk++) {
            float rw = WFt[kk][row];
#pragma unroll
            for (int j4 = 0; j4 < 4; j4++) {
                float4 wv = *(const float4*)&Ws[kk][j0 + 4 * j4];
                o[4 * j4 + 0] += rw * wv.x; o[4 * j4 + 1] += rw * wv.y;
                o[4 * j4 + 2] += rw * wv.z; o[4 * j4 + 3] += rw * wv.w;
            }
        }
        float* pp = g_po + (size_t)gid * 4096 + row * 64 + j0;
#pragma unroll
        for (int j4 = 0; j4 < 4; j4++)
            *(float4*)&pp[4 * j4] = make_float4(o[4 * j4], o[4 * j4 + 1], o[4 * j4 + 2], o[4 * j4 + 3]);
    }
}

// ============ wkv phase 2: exclusive prefix of G over chunks (per bh) ============
__global__ void wkv_p2()
{
    const int bh = blockIdx.x;
    const int e = threadIdx.x * 16;
    float run[16];
#pragma unroll
    for (int j = 0; j < 16; j++) run[j] = 0.f;
    for (int ck = 0; ck < 32; ck++) {
        float* p = g_S + (size_t)(bh * 32 + ck) * 4096 + e;
        float t[16];
#pragma unroll
        for (int j4 = 0; j4 < 4; j4++) {
            float4 v = *(const float4*)&p[4 * j4];
            t[4 * j4] = v.x; t[4 * j4 + 1] = v.y; t[4 * j4 + 2] = v.z; t[4 * j4 + 3] = v.w;
        }
#pragma unroll
        for (int j4 = 0; j4 < 4; j4++) {
            float4 v = make_float4(run[4 * j4], run[4 * j4 + 1], run[4 * j4 + 2], run[4 * j4 + 3]);
            *(float4*)&p[4 * j4] = v;
        }
#pragma unroll
        for (int j = 0; j < 16; j++) run[j] += t[j];
    }
}

// ============ wkv phase 3: o = P + R@S_c, bf16-cast + groupnorm + gate (transposed R/A) ======
__global__ void wkv_p3(const float* __restrict__ lnw, const float* __restrict__ lnb)
{
    extern __shared__ float sm[];
    float (*Rt)[PCH]  = (float (*)[PCH])(sm);
    float (*Ss)[PCH]  = (float (*)[PCH])(sm + 1 * 64 * PCH);
    float (*Amt)[PCH] = (float (*)[PCH])(sm + 2 * 64 * PCH);
    __shared__ float mu_s[64], rstd_s[64], lw_s[64], lb_s[64];

    const int gid = blockIdx.x;
    const int bh = gid >> 5, ck = gid & 31;
    const int b = bh >> 5, h = bh & 31;
    const int tid = threadIdx.x;
    const int row = tid & 63, jg = tid >> 6, j0 = jg * 16;

    if (tid < 64) {
        lw_s[tid] = lnw[h * 64 + tid];
        lb_s[tid] = lnb[h * 64 + tid];
    }
    const int t0 = ck * 64;
    const int off = (b * T_) * C_ + h * 64 + (t0 + row) * C_ + j0;

#pragma unroll
    for (int j4 = 0; j4 < 4; j4++) {
        int jj = j0 + 4 * j4;
        float4 r4 = *(const float4*)&g_r[off + 4 * j4];
        Rt[jj + 0][row] = r4.x; Rt[jj + 1][row] = r4.y;
        Rt[jj + 2][row] = r4.z; Rt[jj + 3][row] = r4.w;
        *(float4*)&Ss[row][jj] = *(const float4*)&g_S[(size_t)gid * 4096 + row * 64 + jj];
    }
    float o[16];
    {
        const float* pp = g_po + (size_t)gid * 4096 + row * 64 + j0;
#pragma unroll
        for (int j4 = 0; j4 < 4; j4++) {
            float4 v = *(const float4*)&pp[4 * j4];
            o[4 * j4] = v.x; o[4 * j4 + 1] = v.y; o[4 * j4 + 2] = v.z; o[4 * j4 + 3] = v.w;
        }
    }
    __syncthreads();

    for (int kk = 0; kk < 64; kk++) {
        float rv = Rt[kk][row];
#pragma unroll
        for (int j4 = 0; j4 < 4; j4++) {
            float4 sv = *(const float4*)&Ss[kk][j0 + 4 * j4];
            o[4 * j4 + 0] += rv * sv.x; o[4 * j4 + 1] += rv * sv.y;
            o[4 * j4 + 2] += rv * sv.z; o[4 * j4 + 3] += rv * sv.w;
        }
    }

#pragma unroll
    for (int j = 0; j < 16; j++)
        Amt[j0 + j][row] = __bfloat162float(__float2bfloat16(o[j]));
    __syncthreads();

    if (tid < 64) {
        float m = 0.f;
        for (int j = 0; j < 64; j++) m += Amt[j][tid];
        m *= (1.f / 64.f);
        float v2 = 0.f;
        for (int j = 0; j < 64; j++) { float d = Amt[j][tid] - m; v2 += d * d; }
        v2 *= (1.f / 64.f);
        mu_s[tid] = m;
        rstd_s[tid] = 1.f / sqrtf(v2 + EPS_);
    }
    __syncthreads();

    {
        float m = mu_s[row], rs = rstd_s[row];
#pragma unroll
        for (int j = 0; j < 16; j++) {
            float y = (Amt[j0 + j][row] - m) * rs * lw_s[j0 + j] + lb_s[j0 + j];
            float z = y * g_gt[off + j];
            g_zh[off + j] = __float2half(z);
        }
    }
}

// ---------------- launch ----------------
extern "C" void kernel_launch(void* const* d_in, const int* in_sizes, int n_in,
                              void* d_out, int out_size)
{
    const float* x     = (const float*)d_in[0];
    const float* state = (const float*)d_in[1];
    const float* wkvs  = (const float*)d_in[2];
    const float* tmk   = (const float*)d_in[3];
    const float* tmv   = (const float*)d_in[4];
    const float* tmr   = (const float*)d_in[5];
    const float* tmg   = (const float*)d_in[6];
    const float* tdec  = (const float*)d_in[7];
    const float* tfaa  = (const float*)d_in[8];
    const float* w_r   = (const float*)d_in[9];
    const float* w_k   = (const float*)d_in[10];
    const float* w_v   = (const float*)d_in[11];
    const float* w_g   = (const float*)d_in[12];
    const float* w_o   = (const float*)d_in[13];
    const float* lnw   = (const float*)d_in[14];
    const float* lnb   = (const float*)d_in[15];

    __half *xgh, *zh, *wgh, *wgl, *woh, *wol;
    float *pr, *pk, *pv, *pg;
    cudaGetSymbolAddress((void**)&xgh, g_xgh);
    cudaGetSymbolAddress((void**)&zh,  g_zh);
    cudaGetSymbolAddress((void**)&wgh, g_wgh); cudaGetSymbolAddress((void**)&wgl, g_wgl);
    cudaGetSymbolAddress((void**)&woh, g_woh); cudaGetSymbolAddress((void**)&wol, g_wol);
    cudaGetSymbolAddress((void**)&pr,  g_r);   cudaGetSymbolAddress((void**)&pk,  g_k);
    cudaGetSymbolAddress((void**)&pv,  g_v);   cudaGetSymbolAddress((void**)&pg,  g_gt);

    mix_kernel<<<(NTOT + 255) / 256, 256>>>(x, state, tmk, tmv, tmr, tmg);
    {
        dim3 wgrid((WSZ + 255) / 256, 5);
        wconv5_kernel<<<wgrid, 256>>>(w_r, w_k, w_v, w_g, w_o);
    }

    const int gsm3 = NSTAGE3 * STG3;   // 192KB
    const int gsm2 = NSTAGE3 * STG2;   // 144KB
    cudaFuncSetAttribute(hgemm3x, cudaFuncAttributeMaxDynamicSharedMemorySize, gsm3);
    cudaFuncSetAttribute(hgemm2<0>, cudaFuncAttributeMaxDynamicSharedMemorySize, gsm2);
    cudaFuncSetAttribute(hgemm2<1>, cudaFuncAttributeMaxDynamicSharedMemorySize, gsm2);

    dim3 gg(C_ / 128, M_ / 128);
    dim3 gg3(C_ / 128, M_ / 128, 3);
    hgemm3x<<<gg3, 256, gsm3>>>(pr, pk, pv);
    hgemm2<1><<<gg, 256, gsm2>>>(xgh, wgh, wgl, pg);

    const int p1sm = 6 * 64 * PCH * 4;
    const int p3sm = 3 * 64 * PCH * 4;
    cudaFuncSetAttribute(wkv_p1, cudaFuncAttributeMaxDynamicSharedMemorySize, p1sm);
    cudaFuncSetAttribute(wkv_p3, cudaFuncAttributeMaxDynamicSharedMemorySize, p3sm);
    wkv_p1<<<128 * 32, 256, p1sm>>>(wkvs, tdec, tfaa);
    wkv_p2<<<128, 256>>>();
    wkv_p3<<<128 * 32, 256, p3sm>>>(lnw, lnb);

    hgemm2<0><<<gg, 256, gsm2>>>(zh, woh, wol, (float*)d_out);
}

// round 15
// speedup vs baseline: 1.0767x; 1.0150x over previous
#include <cuda_runtime.h>
#include <cuda_fp16.h>
#include <cuda_bf16.h>
#include <cstdint>

#define B_ 4
#define T_ 2048
#define C_ 2048
#define H_ 32
#define M_ (B_*T_)
#define NTOT (M_*C_)
#define WSZ (C_*C_)
#define EPS_ 0.00064f
#define PCH 68

// ---------------- scratch (static device globals; allocation-free) ----------------
__device__ __half g_xrh[NTOT], g_xrl[NTOT];
__device__ __half g_xkh[NTOT], g_xkl[NTOT];
__device__ __half g_xvh[NTOT], g_xvl[NTOT];
__device__ __half g_xgh[NTOT];
__device__ __half g_zh[NTOT];
__device__ float g_r[NTOT], g_k[NTOT], g_v[NTOT], g_gt[NTOT];
__device__ float g_S[128 * 32 * 4096];
__device__ float g_po[128 * 32 * 4096];
__device__ __half g_wrh[WSZ], g_wrl[WSZ];
__device__ __half g_wkh[WSZ], g_wkl[WSZ];
__device__ __half g_wvh[WSZ], g_wvl[WSZ];
__device__ __half g_wgh[WSZ], g_wgl[WSZ];
__device__ __half g_woh[WSZ], g_wol[WSZ];

// ---------------- PTX helpers (baseline PTX only) ----------------
__device__ __forceinline__ uint32_t smem_u32(const void* p) {
    uint32_t a;
    asm("{ .reg .u64 t; cvta.to.shared.u64 t, %1; cvt.u32.u64 %0, t; }" : "=r"(a) : "l"(p));
    return a;
}
#define CPASYNC16(dst, src) \
    asm volatile("cp.async.cg.shared.global [%0], [%1], 16;" :: "r"(dst), "l"(src))
#define CPCOMMIT() asm volatile("cp.async.commit_group;" ::: "memory")
#define CPWAIT1()  asm volatile("cp.async.wait_group 1;" ::: "memory")
#define CPWAIT0()  asm volatile("cp.async.wait_group 0;" ::: "memory")

__device__ __forceinline__ void ldsm_x4(uint32_t* r, uint32_t addr) {
    asm volatile("ldmatrix.sync.aligned.m8n8.x4.shared.b16 {%0,%1,%2,%3}, [%4];"
                 : "=r"(r[0]), "=r"(r[1]), "=r"(r[2]), "=r"(r[3]) : "r"(addr));
}
__device__ __forceinline__ void mma_f16(float* c, const uint32_t* a, const uint32_t* b) {
    asm volatile(
        "mma.sync.aligned.m16n8k16.row.col.f32.f16.f16.f32 "
        "{%0,%1,%2,%3}, {%4,%5,%6,%7}, {%8,%9}, {%0,%1,%2,%3};"
        : "+f"(c[0]), "+f"(c[1]), "+f"(c[2]), "+f"(c[3])
        : "r"(a[0]), "r"(a[1]), "r"(a[2]), "r"(a[3]), "r"(b[0]), "r"(b[1]));
}

// smem tile: 128 rows x 64 fp16 = 128B/row; 8 chunks of 16B, XOR-swizzled
__device__ __forceinline__ uint32_t swz64(uint32_t row, uint32_t kc) {
    return row * 128 + ((kc ^ (row & 7)) * 16);
}

// ---------------- token-shift mixing -> split fp16 ----------------
__global__ void mix_kernel(const float* __restrict__ x, const float* __restrict__ state,
                           const float* __restrict__ tmk, const float* __restrict__ tmv,
                           const float* __restrict__ tmr, const float* __restrict__ tmg)
{
    int idx = blockIdx.x * 256 + threadIdx.x;
    if (idx >= NTOT) return;
    int c = idx & (C_ - 1);
    int t = (idx >> 11) & (T_ - 1);
    float xc = x[idx];
    float xp = (t == 0) ? state[c] : x[idx - C_];
    float mk = tmk[c], mv = tmv[c], mr = tmr[c], mg = tmg[c];
    float vk = xc * mk + xp * (1.f - mk);
    float vv = xc * mv + xp * (1.f - mv);
    float vr = xc * mr + xp * (1.f - mr);
    float vg = xc * mg + xp * (1.f - mg);
    __half h;
    h = __float2half(vk); g_xkh[idx] = h; g_xkl[idx] = __float2half(vk - __half2float(h));
    h = __float2half(vv); g_xvh[idx] = h; g_xvl[idx] = __float2half(vv - __half2float(h));
    h = __float2half(vr); g_xrh[idx] = h; g_xrl[idx] = __float2half(vr - __half2float(h));
    g_xgh[idx] = __float2half(vg);
}

// ---------------- fp32 -> split fp16 weight conversion (all 5 in one launch) ------------
__global__ void wconv5_kernel(const float* __restrict__ w0, const float* __restrict__ w1,
                              const float* __restrict__ w2, const float* __restrict__ w3,
                              const float* __restrict__ w4)
{
    int idx = blockIdx.x * 256 + threadIdx.x;
    if (idx >= WSZ) return;
    const float* src;
    __half *dh, *dl;
    switch (blockIdx.y) {
        case 0: src = w0; dh = g_wrh; dl = g_wrl; break;
        case 1: src = w1; dh = g_wkh; dl = g_wkl; break;
        case 2: src = w2; dh = g_wvh; dl = g_wvl; break;
        case 3: src = w3; dh = g_wgh; dl = g_wgl; break;
        default: src = w4; dh = g_woh; dl = g_wol; break;
    }
    float v = src[idx];
    __half h = __float2half(v);
    dh[idx] = h;
    dl[idx] = __float2half(v - __half2float(h));
}

// ======== 3-term HMMA GEMM (r,k,v fused via blockIdx.z) — R10-proven ========
#define NSTAGE3 3
#define STG3 65536
__launch_bounds__(256)
__global__ void hgemm3x(float* __restrict__ C0, float* __restrict__ C1, float* __restrict__ C2)
{
    extern __shared__ __align__(128) char smem[];
    const uint32_t sb = smem_u32(smem);
    const int tid = threadIdx.x;
    const int wid = tid >> 5;
    const int lid = tid & 31;
    const int warp_m = wid >> 1;
    const int warp_n = wid & 1;
    const int bm = blockIdx.y * 128, bn = blockIdx.x * 128;
    const int mat = blockIdx.z;

    const __half* Ah = (mat == 0) ? g_xrh : (mat == 1) ? g_xkh : g_xvh;
    const __half* Al = (mat == 0) ? g_xrl : (mat == 1) ? g_xkl : g_xvl;
    const __half* Bh = (mat == 0) ? g_wrh : (mat == 1) ? g_wkh : g_wvh;
    const __half* Bl = (mat == 0) ? g_wrl : (mat == 1) ? g_wkl : g_wvl;
    float* Cmat = (mat == 0) ? C0 : (mat == 1) ? C1 : C2;

    const __half* mats[4] = { Ah, Al, Bh, Bl };
    const int rbase[4] = { bm, bm, bn, bn };

    auto load_stage = [&](int s, int p) {
        const int k0 = s * 64;
        const uint32_t sbase = sb + p * STG3;
#pragma unroll
        for (int m = 0; m < 4; m++) {
            const __half* src = mats[m] + (size_t)rbase[m] * C_ + k0;
            const uint32_t tb = sbase + m * 16384;
#pragma unroll
            for (int i = 0; i < 4; i++) {
                int chunk = tid + 256 * i;
                int row = chunk >> 3, kc = chunk & 7;
                CPASYNC16(tb + swz64(row, kc), (const char*)(src + (size_t)row * C_) + kc * 16);
            }
        }
    };

    float acc[2][8][4];
#pragma unroll
    for (int mb = 0; mb < 2; mb++)
#pragma unroll
        for (int nf = 0; nf < 8; nf++)
#pragma unroll
            for (int q = 0; q < 4; q++) acc[mb][nf][q] = 0.f;

    load_stage(0, 0); CPCOMMIT();
    load_stage(1, 1); CPCOMMIT();

    const int KS = C_ / 64;
    const uint32_t a_row = lid & 15;
    const uint32_t a_kc  = lid >> 4;
    const uint32_t b_row = (lid & 7) + ((lid >> 4) & 1) * 8;
    const uint32_t b_kc  = (lid >> 3) & 1;

    for (int ks = 0; ks < KS; ks++) {
        CPWAIT1();
        __syncthreads();
        if (ks + 2 < KS) load_stage(ks + 2, (ks + 2) % NSTAGE3);
        CPCOMMIT();

        const uint32_t sbase = sb + (ks % NSTAGE3) * STG3;
#pragma unroll
        for (int kk = 0; kk < 4; kk++) {
            uint32_t ah[2][4], al[2][4];
#pragma unroll
            for (int mb = 0; mb < 2; mb++) {
                uint32_t row = warp_m * 32 + mb * 16 + a_row;
                uint32_t off = swz64(row, kk * 2 + a_kc);
                ldsm_x4(ah[mb], sbase + off);
                ldsm_x4(al[mb], sbase + 16384 + off);
            }
            uint32_t bh[8][2], bl[8][2];
#pragma unroll
            for (int nb = 0; nb < 4; nb++) {
                uint32_t row = warp_n * 64 + nb * 16 + b_row;
                uint32_t off = swz64(row, kk * 2 + b_kc);
                uint32_t t[4];
                ldsm_x4(t, sbase + 32768 + off);
                bh[nb * 2][0] = t[0]; bh[nb * 2][1] = t[1];
                bh[nb * 2 + 1][0] = t[2]; bh[nb * 2 + 1][1] = t[3];
                ldsm_x4(t, sbase + 49152 + off);
                bl[nb * 2][0] = t[0]; bl[nb * 2][1] = t[1];
                bl[nb * 2 + 1][0] = t[2]; bl[nb * 2 + 1][1] = t[3];
            }
#pragma unroll
            for (int mb = 0; mb < 2; mb++)
#pragma unroll
                for (int nf = 0; nf < 8; nf++) {
                    mma_f16(acc[mb][nf], ah[mb], bh[nf]);
                    mma_f16(acc[mb][nf], ah[mb], bl[nf]);
                    mma_f16(acc[mb][nf], al[mb], bh[nf]);
                }
        }
    }
    CPWAIT0();

#pragma unroll
    for (int mb = 0; mb < 2; mb++) {
        int r0 = bm + warp_m * 32 + mb * 16 + (lid >> 2);
#pragma unroll
        for (int nf = 0; nf < 8; nf++) {
            int cc = bn + warp_n * 64 + nf * 8 + (lid & 3) * 2;
            *(float2*)&Cmat[(size_t)r0 * C_ + cc] = make_float2(acc[mb][nf][0], acc[mb][nf][1]);
            *(float2*)&Cmat[(size_t)(r0 + 8) * C_ + cc] = make_float2(acc[mb][nf][2], acc[mb][nf][3]);
        }
    }
}

// ======== 2-term HMMA GEMM (g / w_o): C = Ah*Bh + Ah*Bl — R10-proven ========
#define STG2 49152
template<int ACT>
__launch_bounds__(256)
__global__ void hgemm2(const __half* __restrict__ Ah,
                       const __half* __restrict__ Bh, const __half* __restrict__ Bl,
                       float* __restrict__ Cmat)
{
    extern __shared__ __align__(128) char smem[];
    const uint32_t sb = smem_u32(smem);
    const int tid = threadIdx.x;
    const int wid = tid >> 5;
    const int lid = tid & 31;
    const int warp_m = wid >> 1;
    const int warp_n = wid & 1;
    const int bm = blockIdx.y * 128, bn = blockIdx.x * 128;

    const __half* mats[3] = { Ah, Bh, Bl };
    const int rbase[3] = { bm, bn, bn };

    auto load_stage = [&](int s, int p) {
        const int k0 = s * 64;
        const uint32_t sbase = sb + p * STG2;
#pragma unroll
        for (int m = 0; m < 3; m++) {
            const __half* src = mats[m] + (size_t)rbase[m] * C_ + k0;
            const uint32_t tb = sbase + m * 16384;
#pragma unroll
            for (int i = 0; i < 4; i++) {
                int chunk = tid + 256 * i;
                int row = chunk >> 3, kc = chunk & 7;
                CPASYNC16(tb + swz64(row, kc), (const char*)(src + (size_t)row * C_) + kc * 16);
            }
        }
    };

    float acc[2][8][4];
#pragma unroll
    for (int mb = 0; mb < 2; mb++)
#pragma unroll
        for (int nf = 0; nf < 8; nf++)
#pragma unroll
            for (int q = 0; q < 4; q++) acc[mb][nf][q] = 0.f;

    load_stage(0, 0); CPCOMMIT();
    load_stage(1, 1); CPCOMMIT();

    const int KS = C_ / 64;
    const uint32_t a_row = lid & 15;
    const uint32_t a_kc  = lid >> 4;
    const uint32_t b_row = (lid & 7) + ((lid >> 4) & 1) * 8;
    const uint32_t b_kc  = (lid >> 3) & 1;

    for (int ks = 0; ks < KS; ks++) {
        CPWAIT1();
        __syncthreads();
        if (ks + 2 < KS) load_stage(ks + 2, (ks + 2) % NSTAGE3);
        CPCOMMIT();

        const uint32_t sbase = sb + (ks % NSTAGE3) * STG2;
#pragma unroll
        for (int kk = 0; kk < 4; kk++) {
            uint32_t ah[2][4];
#pragma unroll
            for (int mb = 0; mb < 2; mb++) {
                uint32_t row = warp_m * 32 + mb * 16 + a_row;
                ldsm_x4(ah[mb], sbase + swz64(row, kk * 2 + a_kc));
            }
            uint32_t bh[8][2], bl[8][2];
#pragma unroll
            for (int nb = 0; nb < 4; nb++) {
                uint32_t row = warp_n * 64 + nb * 16 + b_row;
                uint32_t off = swz64(row, kk * 2 + b_kc);
                uint32_t t[4];
                ldsm_x4(t, sbase + 16384 + off);
                bh[nb * 2][0] = t[0]; bh[nb * 2][1] = t[1];
                bh[nb * 2 + 1][0] = t[2]; bh[nb * 2 + 1][1] = t[3];
                ldsm_x4(t, sbase + 32768 + off);
                bl[nb * 2][0] = t[0]; bl[nb * 2][1] = t[1];
                bl[nb * 2 + 1][0] = t[2]; bl[nb * 2 + 1][1] = t[3];
            }
#pragma unroll
            for (int mb = 0; mb < 2; mb++)
#pragma unroll
                for (int nf = 0; nf < 8; nf++) {
                    mma_f16(acc[mb][nf], ah[mb], bh[nf]);
                    mma_f16(acc[mb][nf], ah[mb], bl[nf]);
                }
        }
    }
    CPWAIT0();

#pragma unroll
    for (int mb = 0; mb < 2; mb++) {
        int r0 = bm + warp_m * 32 + mb * 16 + (lid >> 2);
#pragma unroll
        for (int nf = 0; nf < 8; nf++) {
            int cc = bn + warp_n * 64 + nf * 8 + (lid & 3) * 2;
            float v0 = acc[mb][nf][0], v1 = acc[mb][nf][1];
            float v2 = acc[mb][nf][2], v3 = acc[mb][nf][3];
            if (ACT == 1) {
                v0 = v0 / (1.f + expf(-v0)); v1 = v1 / (1.f + expf(-v1));
                v2 = v2 / (1.f + expf(-v2)); v3 = v3 / (1.f + expf(-v3));
            }
            *(float2*)&Cmat[(size_t)r0 * C_ + cc] = make_float2(v0, v1);
            *(float2*)&Cmat[(size_t)(r0 + 8) * C_ + cc] = make_float2(v2, v3);
        }
    }
}

// ============ wkv phase 1: conflict-free layouts + triangular skips ============
__global__ void wkv_p1(const float* __restrict__ wkvstate,
                       const float* __restrict__ time_decay,
                       const float* __restrict__ time_faaaa)
{
    extern __shared__ float sm[];
    float (*Rt)[PCH]  = (float (*)[PCH])(sm);
    float (*Ks)[PCH]  = (float (*)[PCH])(sm + 1 * 64 * PCH);
    float (*Vs)[PCH]  = (float (*)[PCH])(sm + 2 * 64 * PCH);
    float (*Amt)[PCH] = (float (*)[PCH])(sm + 3 * 64 * PCH);
    float (*WFt)[PCH] = (float (*)[PCH])(sm + 4 * 64 * PCH);
    float (*Ws)[PCH]  = (float (*)[PCH])(sm + 5 * 64 * PCH);
    __shared__ float ew[64], uu[64], bonus[64], bpart[4][64];

    const int gid = blockIdx.x;
    const int bh = gid >> 5, ck = gid & 31;
    const int b = bh >> 5, h = bh & 31;
    const int tid = threadIdx.x;
    const int row = tid & 63, jg = tid >> 6, j0 = jg * 16;
    const int wr0 = (tid & 32) ? 32 : 0;   // warp's min row

    if (tid < 64) {
        ew[tid] = expf(time_decay[h * 64 + tid]);
        uu[tid] = time_faaaa[h * 64 + tid];
    }
    const float* W0 = wkvstate + h * 64 * 64;
#pragma unroll
    for (int j4 = 0; j4 < 4; j4++)
        *(float4*)&Ws[row][j0 + 4 * j4] = *(const float4*)&W0[row * 64 + j0 + 4 * j4];

    const int t0 = ck * 64;
    const int off = (b * T_) * C_ + h * 64 + (t0 + row) * C_ + j0;
    float4 r4[4], k4[4], v4[4];
#pragma unroll
    for (int j4 = 0; j4 < 4; j4++) {
        r4[j4] = *(const float4*)&g_r[off + 4 * j4];
        k4[j4] = *(const float4*)&g_k[off + 4 * j4];
        v4[j4] = *(const float4*)&g_v[off + 4 * j4];
        int jj = j0 + 4 * j4;
        *(float4*)&Vs[row][jj] = v4[j4];
        Rt[jj + 0][row] = r4[j4].x; Rt[jj + 1][row] = r4[j4].y;
        Rt[jj + 2][row] = r4[j4].z; Rt[jj + 3][row] = r4[j4].w;
    }
    __syncthreads();

    // WFt = (r * w^t)^T ; Ks = k * w^(T-1-q) (pre-scaled); bonus partials with raw k
    {
        float tg = (float)(t0 + row);
        float qb = (float)(T_ - 1 - (t0 + row));
        float bp = 0.f;
#pragma unroll
        for (int j4 = 0; j4 < 4; j4++) {
            int jj = j0 + 4 * j4;
            WFt[jj + 0][row] = r4[j4].x * expf(-tg * ew[jj + 0]);
            WFt[jj + 1][row] = r4[j4].y * expf(-tg * ew[jj + 1]);
            WFt[jj + 2][row] = r4[j4].z * expf(-tg * ew[jj + 2]);
            WFt[jj + 3][row] = r4[j4].w * expf(-tg * ew[jj + 3]);
            bp += r4[j4].x * k4[j4].x * uu[jj + 0] + r4[j4].y * k4[j4].y * uu[jj + 1]
                + r4[j4].z * k4[j4].z * uu[jj + 2] + r4[j4].w * k4[j4].w * uu[jj + 3];
            float4 k2;
            k2.x = k4[j4].x * expf(-qb * ew[jj + 0]);
            k2.y = k4[j4].y * expf(-qb * ew[jj + 1]);
            k2.z = k4[j4].z * expf(-qb * ew[jj + 2]);
            k2.w = k4[j4].w * expf(-qb * ew[jj + 3]);
            *(float4*)&Ks[row][jj] = k2;
        }
        bpart[jg][row] = bp;
    }
    __syncthreads();

    if (tid < 64)
        bonus[tid] = bpart[0][tid] + bpart[1][tid] + bpart[2][tid] + bpart[3][tid];

    // G = K2^T V  (row = k-index)
    {
        float ga[16];
#pragma unroll
        for (int j = 0; j < 16; j++) ga[j] = 0.f;
        for (int q = 0; q < 64; q++) {
            float kv = Ks[q][row];
#pragma unroll
            for (int j4 = 0; j4 < 4; j4++) {
                float4 vv = *(const float4*)&Vs[q][j0 + 4 * j4];
                ga[4 * j4 + 0] += kv * vv.x; ga[4 * j4 + 1] += kv * vv.y;
                ga[4 * j4 + 2] += kv * vv.z; ga[4 * j4 + 3] += kv * vv.w;
            }
        }
        float* gp = g_S + (size_t)gid * 4096 + row * 64 + j0;
#pragma unroll
        for (int j4 = 0; j4 < 4; j4++)
            *(float4*)&gp[4 * j4] = make_float4(ga[4 * j4], ga[4 * j4 + 1], ga[4 * j4 + 2], ga[4 * j4 + 3]);
    }

    // A = R K2^T (strict lower). Whole-warp skip when block entirely above diagonal
    // (rows <= wr0+31 and j0 >= wr0+31 -> mask (j0+j < row) always false). Exact zeros.
    {
        float a[16];
#pragma unroll
        for (int j = 0; j < 16; j++) a[j] = 0.f;
        if (j0 < wr0 + 31) {
            for (int kb = 0; kb < 64; kb += 4) {
                float r0v = Rt[kb + 0][row], r1v = Rt[kb + 1][row];
                float r2v = Rt[kb + 2][row], r3v = Rt[kb + 3][row];
#pragma unroll
                for (int j = 0; j < 16; j++) {
                    float4 kv = *(const float4*)&Ks[j0 + j][kb];
                    a[j] += r0v * kv.x + r1v * kv.y + r2v * kv.z + r3v * kv.w;
                }
            }
        }
#pragma unroll
        for (int j = 0; j < 16; j++)
            Amt[j0 + j][row] = (j0 + j < row) ? a[j] : 0.f;
    }
    __syncthreads();

    // P = A V (q < row; Amt exactly zero for q >= row) + bonus*v + WF @ W0
    {
        float o[16];
#pragma unroll
        for (int j = 0; j < 16; j++) o[j] = 0.f;
        // uniform part: q in [0, wr0)
        for (int q = 0; q < wr0; q++) {
            float av = Amt[q][row];
#pragma unroll
            for (int j4 = 0; j4 < 4; j4++) {
                float4 vv = *(const float4*)&Vs[q][j0 + 4 * j4];
                o[4 * j4 + 0] += av * vv.x; o[4 * j4 + 1] += av * vv.y;
                o[4 * j4 + 2] += av * vv.z; o[4 * j4 + 3] += av * vv.w;
            }
        }
        // ragged diagonal part: q in [wr0, row)
        for (int q = wr0; q < row; q++) {
            float av = Amt[q][row];
#pragma unroll
            for (int j4 = 0; j4 < 4; j4++) {
                float4 vv = *(const float4*)&Vs[q][j0 + 4 * j4];
                o[4 * j4 + 0] += av * vv.x; o[4 * j4 + 1] += av * vv.y;
                o[4 * j4 + 2] += av * vv.z; o[4 * j4 + 3] += av * vv.w;
            }
        }
        {
            float bb = bonus[row];
#pragma unroll
            for (int j4 = 0; j4 < 4; j4++) {
                o[4 * j4 + 0] += bb * v4[j4].x; o[4 * j4 + 1] += bb * v4[j4].y;
                o[4 * j4 + 2] += bb * v4[j4].z; o[4 * j4 + 3] += bb * v4[j4].w;
            }
        }
        for (int kk = 0; kk < 64; kk++) {
            float rw = WFt[kk][row];
#pragma unroll
            for (int j4 = 0; j4 < 4; j4++) {
                float4 wv = *(const float4*)&Ws[kk][j0 + 4 * j4];
                o[4 * j4 + 0] += rw * wv.x; o[4 * j4 + 1] += rw * wv.y;
                o[4 * j4 + 2] += rw * wv.z; o[4 * j4 + 3] += rw * wv.w;
            }
        }
        float* pp = g_po + (size_t)gid * 4096 + row * 64 + j0;
#pragma unroll
        for (int j4 = 0; j4 < 4; j4++)
            *(float4*)&pp[4 * j4] = make_float4(o[4 * j4], o[4 * j4 + 1], o[4 * j4 + 2], o[4 * j4 + 3]);
    }
}

// ============ wkv phase 2: exclusive prefix of G over chunks (per bh) ============
__global__ void wkv_p2()
{
    const int bh = blockIdx.x;
    const int e = threadIdx.x * 16;
    float run[16];
#pragma unroll
    for (int j = 0; j < 16; j++) run[j] = 0.f;
    for (int ck = 0; ck < 32; ck++) {
        float* p = g_S + (size_t)(bh * 32 + ck) * 4096 + e;
        float t[16];
#pragma unroll
        for (int j4 = 0; j4 < 4; j4++) {
            float4 v = *(const float4*)&p[4 * j4];
            t[4 * j4] = v.x; t[4 * j4 + 1] = v.y; t[4 * j4 + 2] = v.z; t[4 * j4 + 3] = v.w;
        }
#pragma unroll
        for (int j4 = 0; j4 < 4; j4++) {
            float4 v = make_float4(run[4 * j4], run[4 * j4 + 1], run[4 * j4 + 2], run[4 * j4 + 3]);
            *(float4*)&p[4 * j4] = v;
        }
#pragma unroll
        for (int j = 0; j < 16; j++) run[j] += t[j];
    }
}

// ============ wkv phase 3: o = P + R@S_c, bf16-cast + groupnorm + gate ============
__global__ void wkv_p3(const float* __restrict__ lnw, const float* __restrict__ lnb)
{
    extern __shared__ float sm[];
    float (*Rt)[PCH]  = (float (*)[PCH])(sm);
    float (*Ss)[PCH]  = (float (*)[PCH])(sm + 1 * 64 * PCH);
    float (*Amt)[PCH] = (float (*)[PCH])(sm + 2 * 64 * PCH);
    __shared__ float mu_s[64], rstd_s[64], lw_s[64], lb_s[64];

    const int gid = blockIdx.x;
    const int bh = gid >> 5, ck = gid & 31;
    const int b = bh >> 5, h = bh & 31;
    const int tid = threadIdx.x;
    const int row = tid & 63, jg = tid >> 6, j0 = jg * 16;

    if (tid < 64) {
        lw_s[tid] = lnw[h * 64 + tid];
        lb_s[tid] = lnb[h * 64 + tid];
    }
    const int t0 = ck * 64;
    const int off = (b * T_) * C_ + h * 64 + (t0 + row) * C_ + j0;

#pragma unroll
    for (int j4 = 0; j4 < 4; j4++) {
        int jj = j0 + 4 * j4;
        float4 r4 = *(const float4*)&g_r[off + 4 * j4];
        Rt[jj + 0][row] = r4.x; Rt[jj + 1][row] = r4.y;
        Rt[jj + 2][row] = r4.z; Rt[jj + 3][row] = r4.w;
        *(float4*)&Ss[row][jj] = *(const float4*)&g_S[(size_t)gid * 4096 + row * 64 + jj];
    }
    float o[16];
    {
        const float* pp = g_po + (size_t)gid * 4096 + row * 64 + j0;
#pragma unroll
        for (int j4 = 0; j4 < 4; j4++) {
            float4 v = *(const float4*)&pp[4 * j4];
            o[4 * j4] = v.x; o[4 * j4 + 1] = v.y; o[4 * j4 + 2] = v.z; o[4 * j4 + 3] = v.w;
        }
    }
    __syncthreads();

    for (int kk = 0; kk < 64; kk++) {
        float rv = Rt[kk][row];
#pragma unroll
        for (int j4 = 0; j4 < 4; j4++) {
            float4 sv = *(const float4*)&Ss[kk][j0 + 4 * j4];
            o[4 * j4 + 0] += rv * sv.x; o[4 * j4 + 1] += rv * sv.y;
            o[4 * j4 + 2] += rv * sv.z; o[4 * j4 + 3] += rv * sv.w;
        }
    }

#pragma unroll
    for (int j = 0; j < 16; j++)
        Amt[j0 + j][row] = __bfloat162float(__float2bfloat16(o[j]));
    __syncthreads();

    if (tid < 64) {
        float m = 0.f;
        for (int j = 0; j < 64; j++) m += Amt[j][tid];
        m *= (1.f / 64.f);
        float v2 = 0.f;
        for (int j = 0; j < 64; j++) { float d = Amt[j][tid] - m; v2 += d * d; }
        v2 *= (1.f / 64.f);
        mu_s[tid] = m;
        rstd_s[tid] = 1.f / sqrtf(v2 + EPS_);
    }
    __syncthreads();

    {
        float m = mu_s[row], rs = rstd_s[row];
#pragma unroll
        for (int j = 0; j < 16; j++) {
            float y = (Amt[j0 + j][row] - m) * rs * lw_s[j0 + j] + lb_s[j0 + j];
            float z = y * g_gt[off + j];
            g_zh[off + j] = __float2half(z);
        }
    }
}

// ---------------- launch ----------------
extern "C" void kernel_launch(void* const* d_in, const int* in_sizes, int n_in,
                              void* d_out, int out_size)
{
    const float* x     = (const float*)d_in[0];
    const float* state = (const float*)d_in[1];
    const float* wkvs  = (const float*)d_in[2];
    const float* tmk   = (const float*)d_in[3];
    const float* tmv   = (const float*)d_in[4];
    const float* tmr   = (const float*)d_in[5];
    const float* tmg   = (const float*)d_in[6];
    const float* tdec  = (const float*)d_in[7];
    const float* tfaa  = (const float*)d_in[8];
    const float* w_r   = (const float*)d_in[9];
    const float* w_k   = (const float*)d_in[10];
    const float* w_v   = (const float*)d_in[11];
    const float* w_g   = (const float*)d_in[12];
    const float* w_o   = (const float*)d_in[13];
    const float* lnw   = (const float*)d_in[14];
    const float* lnb   = (const float*)d_in[15];

    __half *xgh, *zh, *wgh, *wgl, *woh, *wol;
    float *pr, *pk, *pv, *pg;
    cudaGetSymbolAddress((void**)&xgh, g_xgh);
    cudaGetSymbolAddress((void**)&zh,  g_zh);
    cudaGetSymbolAddress((void**)&wgh, g_wgh); cudaGetSymbolAddress((void**)&wgl, g_wgl);
    cudaGetSymbolAddress((void**)&woh, g_woh); cudaGetSymbolAddress((void**)&wol, g_wol);
    cudaGetSymbolAddress((void**)&pr,  g_r);   cudaGetSymbolAddress((void**)&pk,  g_k);
    cudaGetSymbolAddress((void**)&pv,  g_v);   cudaGetSymbolAddress((void**)&pg,  g_gt);

    // one-time stream/event creation (host-side resources; no device memory)
    static cudaStream_t s2 = nullptr;
    static cudaEvent_t evA = nullptr, evB = nullptr;
    if (s2 == nullptr) {
        cudaStreamCreateWithFlags(&s2, cudaStreamNonBlocking);
        cudaEventCreateWithFlags(&evA, cudaEventDisableTiming);
        cudaEventCreateWithFlags(&evB, cudaEventDisableTiming);
    }

    mix_kernel<<<(NTOT + 255) / 256, 256>>>(x, state, tmk, tmv, tmr, tmg);
    {
        dim3 wgrid((WSZ + 255) / 256, 5);
        wconv5_kernel<<<wgrid, 256>>>(w_r, w_k, w_v, w_g, w_o);
    }

    const int gsm3 = NSTAGE3 * STG3;   // 192KB
    const int gsm2 = NSTAGE3 * STG2;   // 144KB
    cudaFuncSetAttribute(hgemm3x, cudaFuncAttributeMaxDynamicSharedMemorySize, gsm3);
    cudaFuncSetAttribute(hgemm2<0>, cudaFuncAttributeMaxDynamicSharedMemorySize, gsm2);
    cudaFuncSetAttribute(hgemm2<1>, cudaFuncAttributeMaxDynamicSharedMemorySize, gsm2);

    dim3 gg(C_ / 128, M_ / 128);
    dim3 gg3(C_ / 128, M_ / 128, 3);

    // fork: g-projection GEMM runs concurrently with r/k/v GEMM + wkv p1/p2
    cudaEventRecord(evA, 0);
    cudaStreamWaitEvent(s2, evA, 0);
    hgemm2<1><<<gg, 256, gsm2, s2>>>(xgh, wgh, wgl, pg);
    cudaEventRecord(evB, s2);

    hgemm3x<<<gg3, 256, gsm3>>>(pr, pk, pv);

    const int p1sm = 6 * 64 * PCH * 4;
    const int p3sm = 3 * 64 * PCH * 4;
    cudaFuncSetAttribute(wkv_p1, cudaFuncAttributeMaxDynamicSharedMemorySize, p1sm);
    cudaFuncSetAttribute(wkv_p3, cudaFuncAttributeMaxDynamicSharedMemorySize, p3sm);
    wkv_p1<<<128 * 32, 256, p1sm>>>(wkvs, tdec, tfaa);
    wkv_p2<<<128, 256>>>();

    // join: p3 needs g_gt from the g-projection GEMM
    cudaStreamWaitEvent(0, evB, 0);
    wkv_p3<<<128 * 32, 256, p3sm>>>(lnw, lnb);

    hgemm2<0><<<gg, 256, gsm2>>>(zh, woh, wol, (float*)d_out);
}